// round 15
// baseline (speedup 1.0000x reference)
#include <cuda_runtime.h>
#include <math.h>

#define BDIM 256
#define LDIM 8192
#define EDIM 64
#define NP   2731      // patch-start candidates (multiples of 3): ceil(8192/3)
#define NQ   2736      // cs3 entries (q >= NP clamped to total)
#define CH   22        // chunk size in p-units (128 chunks cover 2731)
#define NCHUNK 128
#define NTHREADS 512
#define TPT 16         // tokens per thread
#define NBINS 68       // 0..12 len3, 16..64 len12, 66 dummy
#define NWALKW 4
#define LOG2_9 3.169925001442312f

struct SmemLayout {
    float w2s[EDIM * 65];            // padded rows (cp.async filled)
    unsigned short cs3[NQ];          // prefix sums at multiples of 3 (+clamped tail)
    unsigned int nbA[NTHREADS];      // each thread's tw[3]
    unsigned int nbB[NTHREADS];      // each thread's tw[0]
    unsigned int nbC[NTHREADS];      // token p0+4
    unsigned char nxt[NP + 8];       // step (1 or 4)
    unsigned char nxt2[NP + 8];
    unsigned char nxt4[NP + 8];
    float term[160];                 // boundary entropy LUT (bit-exact ref path)
    float clrep[12 * 32];            // c*log2(c), per-lane replicated
    float dlrep[12 * 32];            // delta LUT, per-lane replicated
    unsigned int exitsW[NCHUNK];
    unsigned int mfull[NCHUNK];
    unsigned char wtotE[8];
    unsigned char esel[NCHUNK + 4];
    int histW[NWALKW][NBINS];
    int NvW[NWALKW];
    int wscan[16];
    int tailS, tailLen;
    float hsum[EDIM];
};

__global__ void __launch_bounds__(NTHREADS, 2)
ep_kernel(const int* __restrict__ x,
          const float* __restrict__ w1,
          const float* __restrict__ b1,
          const float* __restrict__ w2,
          const float* __restrict__ b2,
          float* __restrict__ out)
{
    extern __shared__ unsigned char raw[];
    SmemLayout* sm = (SmemLayout*)raw;
    const int tid = threadIdx.x;
    const int lane = tid & 31;
    const int wid = tid >> 5;
    const int row = blockIdx.x;
    const int p0 = tid * TPT;

    // ---- stage own 16 tokens into registers; publish neighbor words ----
    const int4* xv = (const int4*)(x + (size_t)row * LDIM) + tid * 4;
    unsigned int tw[4];
    int localSum = 0;
    #pragma unroll
    for (int k = 0; k < 4; k++) {
        int4 v = xv[k];
        unsigned int w = (unsigned int)v.x | ((unsigned int)v.y << 8) |
                         ((unsigned int)v.z << 16) | ((unsigned int)v.w << 24);
        tw[k] = w;
        localSum += v.x + v.y + v.z + v.w;
    }
    sm->nbA[tid] = tw[3];
    sm->nbB[tid] = tw[0];
    sm->nbC[tid] = tw[1] & 0xFF;

    // ---- prefetch w1/b1/b2 into registers ----
    float wv1 = 0.0f, bv1 = 0.0f, bv2 = 0.0f;
    if (tid < EDIM) { wv1 = w1[tid]; bv1 = b1[tid]; bv2 = b2[tid]; }

    // ---- w2 -> smem via cp.async, fire-and-forget ----
    {
        #pragma unroll
        for (int r = 0; r < 8; r++) {
            int i = tid + r * NTHREADS;
            unsigned int dst = (unsigned int)__cvta_generic_to_shared(
                &sm->w2s[(i >> 6) * 65 + (i & 63)]);
            const float* src = w2 + i;
            asm volatile("cp.async.ca.shared.global [%0], [%1], 4;\n"
                         :: "r"(dst), "l"(src));
        }
        asm volatile("cp.async.commit_group;\n" ::: "memory");
    }

    // ---- LUTs & init ----
    if (tid < 160) {
        int t = tid >> 4, c = tid & 15;
        float v = 0.0f;
        if (t >= 1 && c <= t) { float pv = (float)c / (float)t; v = -(pv * log2f(pv + 1e-12f)); }
        sm->term[tid] = v;
    }
    if (tid >= 160 && tid < 160 + 384) {
        int i = tid - 160;
        int c = i >> 5;
        float cl  = (c >= 1 && c <= 10) ? (float)c * log2f((float)c) : 0.0f;
        float clm = (c >= 2 && c <= 10) ? (float)(c - 1) * log2f((float)(c - 1)) : 0.0f;
        sm->clrep[i] = cl;
        sm->dlrep[i] = (c >= 1 && c <= 10) ? (cl - clm) : 0.0f;
    }
    for (int i = tid; i < NWALKW * NBINS; i += NTHREADS) ((int*)sm->histW)[i] = 0;
    if (tid == 0) { sm->tailLen = 0; sm->tailS = 0; }
    if (tid < NWALKW) sm->NvW[tid] = 0;
    __syncthreads();

    // ---- block scan of localSum; write cs3 (multiples of 3 only) ----
    {
        int v = localSum;
        #pragma unroll
        for (int d = 1; d < 32; d <<= 1) {
            int n = __shfl_up_sync(0xffffffffu, v, d);
            if (lane >= d) v += n;
        }
        if (lane == 31) sm->wscan[wid] = v;
        __syncthreads();
        if (tid < 16) {
            int wv = sm->wscan[tid];
            #pragma unroll
            for (int d = 1; d < 16; d <<= 1) {
                int n = __shfl_up_sync(0xffffu, wv, d);
                if (tid >= d) wv += n;
            }
            sm->wscan[tid] = wv;
        }
        __syncthreads();
        int base = v - localSum + ((wid > 0) ? sm->wscan[wid - 1] : 0);
        if (tid == 0) sm->cs3[0] = 0;
        int run = base;
        #pragma unroll
        for (int k = 0; k < TPT; k++) {
            run += (int)((tw[k >> 2] >> ((k & 3) * 8)) & 0xFF);
            int idx = p0 + k + 1;
            if (idx % 3 == 0) sm->cs3[idx / 3] = (unsigned short)run;
        }
        if (tid == NTHREADS - 1) {
            #pragma unroll
            for (int q = NP; q < NQ; q++) sm->cs3[q] = (unsigned short)run;
        }
    }

    // ---- entropy: incremental S = sum(c*log2 c), 2 LDS per position ----
    {
        const bool firstT = (tid == 0);
        const bool lastT = (tid == NTHREADS - 1);
        unsigned int pm = firstT ? 0u : sm->nbA[tid - 1];     // tokens p0-4..p0-1
        unsigned int ep = lastT ? 0u : sm->nbB[tid + 1];      // tokens p0+16..p0+19
        unsigned int ep4 = lastT ? 0u : sm->nbC[tid + 1];     // token p0+20

        auto tok = [&](int idx) -> unsigned int {
            if (idx < 0)        return (pm >> ((idx + 4) * 8)) & 0xFF;
            else if (idx < TPT) return (tw[idx >> 2] >> ((idx & 3) * 8)) & 0xFF;
            else if (idx < 20)  return (ep >> ((idx - TPT) * 8)) & 0xFF;
            else                return ep4;
        };

        unsigned int packed = 0;
        #pragma unroll
        for (int i = 0; i <= 4; i++) packed += 1u << (tok(i) << 2);
        if (!firstT) {
            #pragma unroll
            for (int i = -4; i < 0; i++) packed += 1u << (tok(i) << 2);
        }

        const float* cl_lane = sm->clrep + lane;
        const float* dl_lane = sm->dlrep + lane;
        float S = 0.0f;
        {
            unsigned int pk = packed;
            #pragma unroll
            for (int c5 = 0; c5 < 5; c5++) { S += cl_lane[(pk & 15u) << 5]; pk >>= 4; }
        }

        int r0 = (3 - (p0 % 3)) % 3;
        int q = (p0 + r0) / 3;
        float4* outE4 = (float4*)(out + (size_t)BDIM * EDIM + (size_t)row * LDIM + p0);
        float4 stage;

        if (wid == 0 || wid == 15) {
            // ---- full variant with boundary handling (bit-identical to R14) ----
            #pragma unroll
            for (int k = 0; k < TPT; k++) {
                float e = fmaf(-(1.0f / 9.0f), S, LOG2_9);
                if ((firstT && k < 4) || (lastT && k >= TPT - 4)) {
                    int p = p0 + k;
                    int wl = max(0, p - 4), wh = min(LDIM - 1, p + 4);
                    int t = wh - wl + 1;
                    const float* tb = sm->term + (t << 4);
                    unsigned int pk2 = packed;
                    e  = tb[pk2 & 15]; pk2 >>= 4;
                    e += tb[pk2 & 15]; pk2 >>= 4;
                    e += tb[pk2 & 15]; pk2 >>= 4;
                    e += tb[pk2 & 15]; pk2 >>= 4;
                    e += tb[pk2 & 15];
                }
                if ((k & 3) == 0) stage.x = e;
                else if ((k & 3) == 1) stage.y = e;
                else if ((k & 3) == 2) stage.z = e;
                else { stage.w = e; outE4[k >> 2] = stage; }
                if ((k % 3) == r0) { sm->nxt[q] = (e > 1.5f) ? (unsigned char)1 : (unsigned char)4; q++; }
                if (!(firstT && k < 4)) {
                    unsigned int b = tok(k - 4);
                    unsigned int sh = b << 2;
                    unsigned int cb = (packed >> sh) & 15u;
                    S -= dl_lane[cb << 5];
                    packed -= 1u << sh;
                }
                if (!(lastT && k >= TPT - 5)) {
                    unsigned int a = tok(k + 5);
                    unsigned int sh = a << 2;
                    unsigned int ca = (packed >> sh) & 15u;
                    S += dl_lane[(ca + 1u) << 5];
                    packed += 1u << sh;
                }
            }
        } else {
            // ---- clean interior variant: branch-free, unconditional slides ----
            #pragma unroll
            for (int k = 0; k < TPT; k++) {
                float e = fmaf(-(1.0f / 9.0f), S, LOG2_9);
                if ((k & 3) == 0) stage.x = e;
                else if ((k & 3) == 1) stage.y = e;
                else if ((k & 3) == 2) stage.z = e;
                else { stage.w = e; outE4[k >> 2] = stage; }
                if ((k % 3) == r0) { sm->nxt[q] = (e > 1.5f) ? (unsigned char)1 : (unsigned char)4; q++; }
                {
                    unsigned int b = tok(k - 4);
                    unsigned int sh = b << 2;
                    unsigned int cb = (packed >> sh) & 15u;
                    S -= dl_lane[cb << 5];
                    packed -= 1u << sh;
                }
                {
                    unsigned int a = tok(k + 5);
                    unsigned int sh = a << 2;
                    unsigned int ca = (packed >> sh) & 15u;
                    S += dl_lane[(ca + 1u) << 5];
                    packed += 1u << sh;
                }
            }
        }
    }
    __syncthreads();

    // ---- nxt2 ----
    for (int p = tid; p < NP; p += NTHREADS) {
        int u = sm->nxt[p];
        int qq = p + u;
        sm->nxt2[p] = (unsigned char)(u + ((qq < NP) ? (int)sm->nxt[qq] : 4));
    }
    __syncthreads();

    // ---- nxt4 ----
    for (int p = tid; p < NP; p += NTHREADS) {
        int u2 = sm->nxt2[p];
        int q2 = p + u2;
        sm->nxt4[p] = (unsigned char)(u2 + ((q2 < NP) ? (int)sm->nxt2[q2] : 8));
    }
    __syncthreads();

    // ---- speculative chunk walks: 128 chunks x 4 entries = all 512 threads ----
    {
        int chunk = tid >> 2, e = tid & 3;
        int p = chunk * CH + e;
        int pend = min((chunk + 1) * CH, NP);
        while (p + (int)sm->nxt4[p] < pend) p += (int)sm->nxt4[p];
        if (p < pend) {
            int u2 = (int)sm->nxt2[p];
            if (p + u2 < pend) p += u2;
            while (p < pend) p += (int)sm->nxt[p];
        }
        ((unsigned char*)sm->exitsW)[tid] = (unsigned char)(p - pend);
    }
    __syncthreads();

    // ---- warps 0-3: per-warp map scans ----
    if (tid < NCHUNK) {
        unsigned int m = sm->exitsW[tid];
        #pragma unroll
        for (int d = 1; d < 32; d <<= 1) {
            unsigned int pmv = __shfl_up_sync(0xffffffffu, m, d);
            if (lane >= d) {
                unsigned int sel = (pmv & 0x3u) | ((pmv >> 4) & 0x30u) |
                                   ((pmv >> 8) & 0x300u) | ((pmv >> 12) & 0x3000u);
                m = __byte_perm(m, 0, sel);
            }
        }
        sm->mfull[tid] = m;
    }
    __syncthreads();

    // ---- compose warp totals ----
    if (tid == 0) {
        unsigned char E = 0;
        sm->wtotE[0] = 0;
        #pragma unroll
        for (int w = 0; w < 3; w++) {
            unsigned int T = sm->mfull[w * 32 + 31];
            E = (unsigned char)((T >> (8 * E)) & 0x3u);
            sm->wtotE[w + 1] = E;
        }
    }
    __syncthreads();

    // ---- per-chunk entry offsets ----
    if (tid < NCHUNK) {
        if (tid == 0) sm->esel[0] = 0;
        if (tid < NCHUNK - 1) {
            unsigned int Ew = sm->wtotE[tid >> 5];
            sm->esel[tid + 1] = (unsigned char)((sm->mfull[tid] >> (8 * Ew)) & 0x3u);
        }
    }
    __syncthreads();

    // ---- real walk: 128 threads, 6 fixed trips, 4 patches/trip, match_any hist ----
    if (tid < NCHUNK) {
        int p = tid * CH + (int)sm->esel[tid];
        int pend = min((tid + 1) * CH, NP);
        int nv = 0;
        int* hw = sm->histW[wid];

        #pragma unroll 1
        for (int it = 0; it < 6; it++) {
            int key0 = 66, key1 = 66, key2 = 66, key3 = 66;
            if (p < pend) {
                int u1 = (int)sm->nxt[p];
                int u2 = (int)sm->nxt2[p];
                {
                    int qn = p + u1;
                    int j = min(3 * qn, LDIM);
                    int len = j - 3 * p;
                    int S = (int)sm->cs3[qn] - (int)sm->cs3[p];
                    nv++;
                    if (len == 3) key0 = S; else if (len == 12) key0 = 16 + S;
                    else { sm->tailS = S; sm->tailLen = len; }
                }
                int p1 = p + u1;
                if (p1 < pend) {
                    int ul = u2 - u1;
                    int qn = p1 + ul;
                    int j = min(3 * qn, LDIM);
                    int len = j - 3 * p1;
                    int S = (int)sm->cs3[qn] - (int)sm->cs3[p1];
                    nv++;
                    if (len == 3) key1 = S; else if (len == 12) key1 = 16 + S;
                    else { sm->tailS = S; sm->tailLen = len; }
                    int p2 = p + u2;
                    if (p2 < pend) {
                        int u3 = (int)sm->nxt[p2];
                        int u4 = (int)sm->nxt2[p2];
                        {
                            int qn2 = p2 + u3;
                            int j2 = min(3 * qn2, LDIM);
                            int len2 = j2 - 3 * p2;
                            int S2 = (int)sm->cs3[qn2] - (int)sm->cs3[p2];
                            nv++;
                            if (len2 == 3) key2 = S2; else if (len2 == 12) key2 = 16 + S2;
                            else { sm->tailS = S2; sm->tailLen = len2; }
                        }
                        int p3 = p2 + u3;
                        if (p3 < pend) {
                            int ul2 = u4 - u3;
                            int qn3 = p3 + ul2;
                            int j3 = min(3 * qn3, LDIM);
                            int len3 = j3 - 3 * p3;
                            int S3 = (int)sm->cs3[qn3] - (int)sm->cs3[p3];
                            nv++;
                            if (len3 == 3) key3 = S3; else if (len3 == 12) key3 = 16 + S3;
                            else { sm->tailS = S3; sm->tailLen = len3; }
                            p = p2 + u4;
                        } else p = p3;
                    } else p = p2;
                } else p = p1;
            }
            unsigned int g;
            g = __match_any_sync(0xffffffffu, key0);
            if (key0 != 66 && (__ffs(g) - 1) == lane) hw[key0] += __popc(g);
            g = __match_any_sync(0xffffffffu, key1);
            if (key1 != 66 && (__ffs(g) - 1) == lane) hw[key1] += __popc(g);
            g = __match_any_sync(0xffffffffu, key2);
            if (key2 != 66 && (__ffs(g) - 1) == lane) hw[key2] += __popc(g);
            g = __match_any_sync(0xffffffffu, key3);
            if (key3 != 66 && (__ffs(g) - 1) == lane) hw[key3] += __popc(g);
        }
        #pragma unroll
        for (int d = 16; d > 0; d >>= 1) nv += __shfl_down_sync(0xffffffffu, nv, d);
        if (lane == 0) sm->NvW[wid] = nv;
    }
    asm volatile("cp.async.wait_group 0;\n" ::: "memory");
    __syncthreads();

    // ---- hsum[e] = mean over valid patches of relu(mean*w1[e]+b1[e]) ----
    if (tid < EDIM) {
        float acc = 0.0f;
        #pragma unroll
        for (int s = 0; s <= 12; s++) {
            int c = sm->histW[0][s] + sm->histW[1][s] + sm->histW[2][s] + sm->histW[3][s];
            acc += (float)c * fmaxf(fmaf((float)s / 3.0f, wv1, bv1), 0.0f);
        }
        #pragma unroll
        for (int s = 0; s <= 48; s++) {
            int c = sm->histW[0][16 + s] + sm->histW[1][16 + s] +
                    sm->histW[2][16 + s] + sm->histW[3][16 + s];
            acc += (float)c * fmaxf(fmaf((float)s / 12.0f, wv1, bv1), 0.0f);
        }
        if (sm->tailLen > 0)
            acc += fmaxf(fmaf((float)sm->tailS / (float)sm->tailLen, wv1, bv1), 0.0f);
        int Nv = sm->NvW[0] + sm->NvW[1] + sm->NvW[2] + sm->NvW[3];
        sm->hsum[tid] = acc / (float)Nv;
    }
    __syncthreads();

    // ---- vec = hbar @ w2^T + b2 ----
    if (tid < EDIM) {
        const float* wrow = sm->w2s + tid * 65;
        float v = bv2;
        #pragma unroll
        for (int e = 0; e < EDIM; e++) v = fmaf(sm->hsum[e], wrow[e], v);
        out[(size_t)row * EDIM + tid] = v;
    }
}

extern "C" void kernel_launch(void* const* d_in, const int* in_sizes, int n_in,
                              void* d_out, int out_size)
{
    const int*   x  = (const int*)d_in[0];
    const float* w1 = (const float*)d_in[1];
    const float* b1 = (const float*)d_in[2];
    const float* w2 = (const float*)d_in[3];
    const float* b2 = (const float*)d_in[4];
    float* out = (float*)d_out;

    cudaFuncSetAttribute(ep_kernel, cudaFuncAttributeMaxDynamicSharedMemorySize,
                         (int)sizeof(SmemLayout));
    ep_kernel<<<BDIM, NTHREADS, sizeof(SmemLayout)>>>(x, w1, b1, w2, b2, out);
}

// round 16
// speedup vs baseline: 1.0152x; 1.0152x over previous
#include <cuda_runtime.h>
#include <math.h>

#define BDIM 256
#define LDIM 8192
#define EDIM 64
#define NP   2731      // patch-start candidates (multiples of 3): ceil(8192/3)
#define NQ   2736      // cs3 entries (q >= NP clamped to total)
#define CH   22        // chunk size in p-units (128 chunks cover 2731)
#define NCHUNK 128
#define NTHREADS 512
#define TPT 16         // tokens per thread
#define NBINS 68       // 0..12 len3, 16..64 len12, 66 dummy
#define NWALKW 4
#define LOG2_9 3.169925001442312f

struct SmemLayout {
    float w2s[EDIM * 65];            // padded rows (cp.async filled)
    unsigned short cs3[NQ];          // prefix sums at multiples of 3 (+clamped tail)
    unsigned int nbA[NTHREADS];      // each thread's tw[3]
    unsigned int nbB[NTHREADS];      // each thread's tw[0]
    unsigned int nbC[NTHREADS];      // token p0+4
    unsigned char nxt[NP + 8];       // step (1 or 4)
    unsigned char nxt2[NP + 8];
    unsigned char nxt4[NP + 8];
    float term[160];                 // boundary entropy LUT (bit-exact ref path)
    float clrep[12 * 32];            // c*log2(c), per-lane replicated
    float dlrep[12 * 32];            // delta LUT, per-lane replicated
    unsigned int exitsW[NCHUNK];
    unsigned int mfull[NCHUNK];
    unsigned char wtotE[8];
    unsigned char esel[NCHUNK + 4];
    int histW[NWALKW][NBINS];
    int NvW[NWALKW];
    int wscan[16];
    int tailS, tailLen;
    float hsum[EDIM];
};

__global__ void __launch_bounds__(NTHREADS, 2)
ep_kernel(const int* __restrict__ x,
          const float* __restrict__ w1,
          const float* __restrict__ b1,
          const float* __restrict__ w2,
          const float* __restrict__ b2,
          float* __restrict__ out)
{
    extern __shared__ unsigned char raw[];
    SmemLayout* sm = (SmemLayout*)raw;
    const int tid = threadIdx.x;
    const int lane = tid & 31;
    const int wid = tid >> 5;
    const int row = blockIdx.x;
    const int p0 = tid * TPT;

    // ---- stage own 16 tokens into registers; publish neighbor words ----
    const int4* xv = (const int4*)(x + (size_t)row * LDIM) + tid * 4;
    unsigned int tw[4];
    int localSum = 0;
    #pragma unroll
    for (int k = 0; k < 4; k++) {
        int4 v = xv[k];
        unsigned int w = (unsigned int)v.x | ((unsigned int)v.y << 8) |
                         ((unsigned int)v.z << 16) | ((unsigned int)v.w << 24);
        tw[k] = w;
        localSum += v.x + v.y + v.z + v.w;
    }
    sm->nbA[tid] = tw[3];
    sm->nbB[tid] = tw[0];
    sm->nbC[tid] = tw[1] & 0xFF;

    // ---- prefetch w1/b1/b2 into registers ----
    float wv1 = 0.0f, bv1 = 0.0f, bv2 = 0.0f;
    if (tid < EDIM) { wv1 = w1[tid]; bv1 = b1[tid]; bv2 = b2[tid]; }

    // ---- w2 -> smem via cp.async, fire-and-forget ----
    {
        #pragma unroll
        for (int r = 0; r < 8; r++) {
            int i = tid + r * NTHREADS;
            unsigned int dst = (unsigned int)__cvta_generic_to_shared(
                &sm->w2s[(i >> 6) * 65 + (i & 63)]);
            const float* src = w2 + i;
            asm volatile("cp.async.ca.shared.global [%0], [%1], 4;\n"
                         :: "r"(dst), "l"(src));
        }
        asm volatile("cp.async.commit_group;\n" ::: "memory");
    }

    // ---- LUTs & init ----
    if (tid < 160) {
        int t = tid >> 4, c = tid & 15;
        float v = 0.0f;
        if (t >= 1 && c <= t) { float pv = (float)c / (float)t; v = -(pv * log2f(pv + 1e-12f)); }
        sm->term[tid] = v;
    }
    if (tid >= 160 && tid < 160 + 384) {
        int i = tid - 160;
        int c = i >> 5;
        float cl  = (c >= 1 && c <= 10) ? (float)c * log2f((float)c) : 0.0f;
        float clm = (c >= 2 && c <= 10) ? (float)(c - 1) * log2f((float)(c - 1)) : 0.0f;
        sm->clrep[i] = cl;
        sm->dlrep[i] = (c >= 1 && c <= 10) ? (cl - clm) : 0.0f;
    }
    for (int i = tid; i < NWALKW * NBINS; i += NTHREADS) ((int*)sm->histW)[i] = 0;
    if (tid == 0) { sm->tailLen = 0; sm->tailS = 0; }
    if (tid < NWALKW) sm->NvW[tid] = 0;
    __syncthreads();

    // ---- block scan of localSum; write cs3 (multiples of 3 only) ----
    {
        int v = localSum;
        #pragma unroll
        for (int d = 1; d < 32; d <<= 1) {
            int n = __shfl_up_sync(0xffffffffu, v, d);
            if (lane >= d) v += n;
        }
        if (lane == 31) sm->wscan[wid] = v;
        __syncthreads();
        if (tid < 16) {
            int wv = sm->wscan[tid];
            #pragma unroll
            for (int d = 1; d < 16; d <<= 1) {
                int n = __shfl_up_sync(0xffffu, wv, d);
                if (tid >= d) wv += n;
            }
            sm->wscan[tid] = wv;
        }
        __syncthreads();
        int base = v - localSum + ((wid > 0) ? sm->wscan[wid - 1] : 0);
        if (tid == 0) sm->cs3[0] = 0;
        int run = base;
        #pragma unroll
        for (int k = 0; k < TPT; k++) {
            run += (int)((tw[k >> 2] >> ((k & 3) * 8)) & 0xFF);
            int idx = p0 + k + 1;
            if (idx % 3 == 0) sm->cs3[idx / 3] = (unsigned short)run;
        }
        if (tid == NTHREADS - 1) {
            #pragma unroll
            for (int q = NP; q < NQ; q++) sm->cs3[q] = (unsigned short)run;
        }
    }

    // ---- entropy: incremental S = sum(c*log2 c), 2 LDS per position ----
    {
        const bool firstT = (tid == 0);
        const bool lastT = (tid == NTHREADS - 1);
        unsigned int pm = firstT ? 0u : sm->nbA[tid - 1];     // tokens p0-4..p0-1
        unsigned int ep = lastT ? 0u : sm->nbB[tid + 1];      // tokens p0+16..p0+19
        unsigned int ep4 = lastT ? 0u : sm->nbC[tid + 1];     // token p0+20

        auto tok = [&](int idx) -> unsigned int {
            if (idx < 0)        return (pm >> ((idx + 4) * 8)) & 0xFF;
            else if (idx < TPT) return (tw[idx >> 2] >> ((idx & 3) * 8)) & 0xFF;
            else if (idx < 20)  return (ep >> ((idx - TPT) * 8)) & 0xFF;
            else                return ep4;
        };

        unsigned int packed = 0;
        #pragma unroll
        for (int i = 0; i <= 4; i++) packed += 1u << (tok(i) << 2);
        if (!firstT) {
            #pragma unroll
            for (int i = -4; i < 0; i++) packed += 1u << (tok(i) << 2);
        }

        const float* cl_lane = sm->clrep + lane;
        const float* dl_lane = sm->dlrep + lane;
        float S = 0.0f;
        {
            unsigned int pk = packed;
            #pragma unroll
            for (int c5 = 0; c5 < 5; c5++) { S += cl_lane[(pk & 15u) << 5]; pk >>= 4; }
        }

        int r0 = (3 - (p0 % 3)) % 3;
        int q = (p0 + r0) / 3;
        float4* outE4 = (float4*)(out + (size_t)BDIM * EDIM + (size_t)row * LDIM + p0);
        float4 stage;

        if (wid == 0 || wid == 15) {
            // ---- full variant with boundary handling (bit-identical ref path) ----
            #pragma unroll
            for (int k = 0; k < TPT; k++) {
                float e = fmaf(-(1.0f / 9.0f), S, LOG2_9);
                if ((firstT && k < 4) || (lastT && k >= TPT - 4)) {
                    int p = p0 + k;
                    int wl = max(0, p - 4), wh = min(LDIM - 1, p + 4);
                    int t = wh - wl + 1;
                    const float* tb = sm->term + (t << 4);
                    unsigned int pk2 = packed;
                    e  = tb[pk2 & 15]; pk2 >>= 4;
                    e += tb[pk2 & 15]; pk2 >>= 4;
                    e += tb[pk2 & 15]; pk2 >>= 4;
                    e += tb[pk2 & 15]; pk2 >>= 4;
                    e += tb[pk2 & 15];
                }
                if ((k & 3) == 0) stage.x = e;
                else if ((k & 3) == 1) stage.y = e;
                else if ((k & 3) == 2) stage.z = e;
                else { stage.w = e; outE4[k >> 2] = stage; }
                if ((k % 3) == r0) { sm->nxt[q] = (e > 1.5f) ? (unsigned char)1 : (unsigned char)4; q++; }
                if (!(firstT && k < 4)) {
                    unsigned int b = tok(k - 4);
                    unsigned int sh = b << 2;
                    unsigned int cb = (packed >> sh) & 15u;
                    S -= dl_lane[cb << 5];
                    packed -= 1u << sh;
                }
                if (!(lastT && k >= TPT - 5)) {
                    unsigned int a = tok(k + 5);
                    unsigned int sh = a << 2;
                    unsigned int ca = (packed >> sh) & 15u;
                    S += dl_lane[(ca + 1u) << 5];
                    packed += 1u << sh;
                }
            }
        } else {
            // ---- clean interior variant: branch-free, unconditional slides ----
            #pragma unroll
            for (int k = 0; k < TPT; k++) {
                float e = fmaf(-(1.0f / 9.0f), S, LOG2_9);
                if ((k & 3) == 0) stage.x = e;
                else if ((k & 3) == 1) stage.y = e;
                else if ((k & 3) == 2) stage.z = e;
                else { stage.w = e; outE4[k >> 2] = stage; }
                if ((k % 3) == r0) { sm->nxt[q] = (e > 1.5f) ? (unsigned char)1 : (unsigned char)4; q++; }
                {
                    unsigned int b = tok(k - 4);
                    unsigned int sh = b << 2;
                    unsigned int cb = (packed >> sh) & 15u;
                    S -= dl_lane[cb << 5];
                    packed -= 1u << sh;
                }
                {
                    unsigned int a = tok(k + 5);
                    unsigned int sh = a << 2;
                    unsigned int ca = (packed >> sh) & 15u;
                    S += dl_lane[(ca + 1u) << 5];
                    packed += 1u << sh;
                }
            }
        }
    }
    __syncthreads();

    // ---- fused nxt2 + nxt4 build (single phase, one barrier saved) ----
    // nxt2[p] = nxt[p] + nxt[p+nxt[p]] (clamped); nxt4[p] = nxt2[p] + nxt2'[p+nxt2[p]]
    // where nxt2' is recomputed from nxt (no cross-thread dependency on nxt2 stores).
    for (int p = tid; p < NP; p += NTHREADS) {
        int u = sm->nxt[p];
        int q1 = p + u;
        int u2 = u + ((q1 < NP) ? (int)sm->nxt[q1] : 4);
        sm->nxt2[p] = (unsigned char)u2;
        int q2 = p + u2;
        int u4;
        if (q2 < NP) {
            int ua = sm->nxt[q2];
            int q3 = q2 + ua;
            u4 = u2 + ua + ((q3 < NP) ? (int)sm->nxt[q3] : 4);
        } else {
            u4 = u2 + 8;
        }
        sm->nxt4[p] = (unsigned char)u4;
    }
    __syncthreads();

    // ---- speculative chunk walks: 128 chunks x 4 entries = all 512 threads ----
    {
        int chunk = tid >> 2, e = tid & 3;
        int p = chunk * CH + e;
        int pend = min((chunk + 1) * CH, NP);
        while (p + (int)sm->nxt4[p] < pend) p += (int)sm->nxt4[p];
        // finish with at most one nxt2 and then nxt1 steps
        int u2 = (int)sm->nxt2[p];
        if (p + u2 < pend) p += u2;
        while (p < pend) p += (int)sm->nxt[p];
        ((unsigned char*)sm->exitsW)[tid] = (unsigned char)(p - pend);
    }
    __syncthreads();

    // ---- warps 0-3: per-warp map scans ----
    if (tid < NCHUNK) {
        unsigned int m = sm->exitsW[tid];
        #pragma unroll
        for (int d = 1; d < 32; d <<= 1) {
            unsigned int pmv = __shfl_up_sync(0xffffffffu, m, d);
            if (lane >= d) {
                unsigned int sel = (pmv & 0x3u) | ((pmv >> 4) & 0x30u) |
                                   ((pmv >> 8) & 0x300u) | ((pmv >> 12) & 0x3000u);
                m = __byte_perm(m, 0, sel);
            }
        }
        sm->mfull[tid] = m;
    }
    __syncthreads();

    // ---- compose warp totals ----
    if (tid == 0) {
        unsigned char E = 0;
        sm->wtotE[0] = 0;
        #pragma unroll
        for (int w = 0; w < 3; w++) {
            unsigned int T = sm->mfull[w * 32 + 31];
            E = (unsigned char)((T >> (8 * E)) & 0x3u);
            sm->wtotE[w + 1] = E;
        }
    }
    __syncthreads();

    // ---- per-chunk entry offsets ----
    if (tid < NCHUNK) {
        if (tid == 0) sm->esel[0] = 0;
        if (tid < NCHUNK - 1) {
            unsigned int Ew = sm->wtotE[tid >> 5];
            sm->esel[tid + 1] = (unsigned char)((sm->mfull[tid] >> (8 * Ew)) & 0x3u);
        }
    }
    __syncthreads();

    // ---- real walk: 128 threads, 6 fixed trips, 4 patches/trip, match_any hist ----
    if (tid < NCHUNK) {
        int p = tid * CH + (int)sm->esel[tid];
        int pend = min((tid + 1) * CH, NP);
        int nv = 0;
        int* hw = sm->histW[wid];

        #pragma unroll 1
        for (int it = 0; it < 6; it++) {
            int key0 = 66, key1 = 66, key2 = 66, key3 = 66;
            if (p < pend) {
                int u1 = (int)sm->nxt[p];
                int u2 = (int)sm->nxt2[p];
                {
                    int qn = p + u1;
                    int j = min(3 * qn, LDIM);
                    int len = j - 3 * p;
                    int S = (int)sm->cs3[qn] - (int)sm->cs3[p];
                    nv++;
                    if (len == 3) key0 = S; else if (len == 12) key0 = 16 + S;
                    else { sm->tailS = S; sm->tailLen = len; }
                }
                int p1 = p + u1;
                if (p1 < pend) {
                    int ul = u2 - u1;
                    int qn = p1 + ul;
                    int j = min(3 * qn, LDIM);
                    int len = j - 3 * p1;
                    int S = (int)sm->cs3[qn] - (int)sm->cs3[p1];
                    nv++;
                    if (len == 3) key1 = S; else if (len == 12) key1 = 16 + S;
                    else { sm->tailS = S; sm->tailLen = len; }
                    int p2 = p + u2;
                    if (p2 < pend) {
                        int u3 = (int)sm->nxt[p2];
                        int u4 = (int)sm->nxt2[p2];
                        {
                            int qn2 = p2 + u3;
                            int j2 = min(3 * qn2, LDIM);
                            int len2 = j2 - 3 * p2;
                            int S2 = (int)sm->cs3[qn2] - (int)sm->cs3[p2];
                            nv++;
                            if (len2 == 3) key2 = S2; else if (len2 == 12) key2 = 16 + S2;
                            else { sm->tailS = S2; sm->tailLen = len2; }
                        }
                        int p3 = p2 + u3;
                        if (p3 < pend) {
                            int ul2 = u4 - u3;
                            int qn3 = p3 + ul2;
                            int j3 = min(3 * qn3, LDIM);
                            int len3 = j3 - 3 * p3;
                            int S3 = (int)sm->cs3[qn3] - (int)sm->cs3[p3];
                            nv++;
                            if (len3 == 3) key3 = S3; else if (len3 == 12) key3 = 16 + S3;
                            else { sm->tailS = S3; sm->tailLen = len3; }
                            p = p2 + u4;
                        } else p = p3;
                    } else p = p2;
                } else p = p1;
            }
            unsigned int g;
            g = __match_any_sync(0xffffffffu, key0);
            if (key0 != 66 && (__ffs(g) - 1) == lane) hw[key0] += __popc(g);
            g = __match_any_sync(0xffffffffu, key1);
            if (key1 != 66 && (__ffs(g) - 1) == lane) hw[key1] += __popc(g);
            g = __match_any_sync(0xffffffffu, key2);
            if (key2 != 66 && (__ffs(g) - 1) == lane) hw[key2] += __popc(g);
            g = __match_any_sync(0xffffffffu, key3);
            if (key3 != 66 && (__ffs(g) - 1) == lane) hw[key3] += __popc(g);
        }
        #pragma unroll
        for (int d = 16; d > 0; d >>= 1) nv += __shfl_down_sync(0xffffffffu, nv, d);
        if (lane == 0) sm->NvW[wid] = nv;
    }
    asm volatile("cp.async.wait_group 0;\n" ::: "memory");
    __syncthreads();

    // ---- hsum[e] = mean over valid patches of relu(mean*w1[e]+b1[e]) ----
    if (tid < EDIM) {
        float acc = 0.0f;
        #pragma unroll
        for (int s = 0; s <= 12; s++) {
            int c = sm->histW[0][s] + sm->histW[1][s] + sm->histW[2][s] + sm->histW[3][s];
            acc += (float)c * fmaxf(fmaf((float)s / 3.0f, wv1, bv1), 0.0f);
        }
        #pragma unroll
        for (int s = 0; s <= 48; s++) {
            int c = sm->histW[0][16 + s] + sm->histW[1][16 + s] +
                    sm->histW[2][16 + s] + sm->histW[3][16 + s];
            acc += (float)c * fmaxf(fmaf((float)s / 12.0f, wv1, bv1), 0.0f);
        }
        if (sm->tailLen > 0)
            acc += fmaxf(fmaf((float)sm->tailS / (float)sm->tailLen, wv1, bv1), 0.0f);
        int Nv = sm->NvW[0] + sm->NvW[1] + sm->NvW[2] + sm->NvW[3];
        sm->hsum[tid] = acc / (float)Nv;
    }
    __syncthreads();

    // ---- vec = hbar @ w2^T + b2 ----
    if (tid < EDIM) {
        const float* wrow = sm->w2s + tid * 65;
        float v = bv2;
        #pragma unroll
        for (int e = 0; e < EDIM; e++) v = fmaf(sm->hsum[e], wrow[e], v);
        out[(size_t)row * EDIM + tid] = v;
    }
}

extern "C" void kernel_launch(void* const* d_in, const int* in_sizes, int n_in,
                              void* d_out, int out_size)
{
    const int*   x  = (const int*)d_in[0];
    const float* w1 = (const float*)d_in[1];
    const float* b1 = (const float*)d_in[2];
    const float* w2 = (const float*)d_in[3];
    const float* b2 = (const float*)d_in[4];
    float* out = (float*)d_out;

    cudaFuncSetAttribute(ep_kernel, cudaFuncAttributeMaxDynamicSharedMemorySize,
                         (int)sizeof(SmemLayout));
    ep_kernel<<<BDIM, NTHREADS, sizeof(SmemLayout)>>>(x, w1, b1, w2, b2, out);
}